// round 9
// baseline (speedup 1.0000x reference)
#include <cuda_runtime.h>
#include <math.h>

#define IMG 40
#define HW 1600
#define BATCH 256
#define CH 40

typedef unsigned long long u64;

// Ping-pong scratch (131 MB each), device-side only.
__device__ float2 g_bufA[(size_t)BATCH * CH * HW];
__device__ float2 g_bufB[(size_t)BATCH * CH * HW];
__device__ float4 g_D4[HW];   // DFT matrix pre-broadcast: (dre, dre, dim, dim)

template <int B>
__device__ __forceinline__ float2* getbuf() {
    return (B == 0) ? g_bufA : g_bufB;
}

__global__ void init_D_kernel() {
    int idx = blockIdx.x * blockDim.x + threadIdx.x;
    if (idx >= HW) return;
    int k = idx / IMG, n = idx % IMG;
    int m = (k * n) % IMG;
    float theta = 2.0f * 3.14159265358979323846f * (float)m / (float)IMG;
    float s, c;
    sincosf(theta, &s, &c);
    float nrm = rsqrtf((float)IMG);
    // forward D = (c - i s)/sqrt(40), re broadcast in .xy, im broadcast in .zw
    g_D4[idx] = make_float4(c * nrm, c * nrm, -s * nrm, -s * nrm);
}

// ---------------- packed f32x2 helpers ----------------
__device__ __forceinline__ float2 unpack2(u64 v) {
    float lo, hi; asm("mov.b64 {%0, %1}, %2;" : "=f"(lo), "=f"(hi) : "l"(v));
    return make_float2(lo, hi);
}
__device__ __forceinline__ u64 pack2(float lo, float hi) {
    u64 r; asm("mov.b64 %0, {%1, %2};" : "=l"(r) : "f"(lo), "f"(hi)); return r;
}
__device__ __forceinline__ void fma2(u64& a, u64 x, u64 y) {
    asm("fma.rn.f32x2 %0, %1, %2, %0;" : "+l"(a) : "l"(x), "l"(y));
}
__device__ __forceinline__ u64 neg2(u64 a) {   // flip both packed sign bits
    u64 r;
    asm("xor.b64 %0, %1, %2;" : "=l"(r) : "l"(a), "l"(0x8000000080000000ULL));
    return r;
}

#define FFTSMEM (2 * IMG * (IMG + 1) * 16)   // ZT + D4 = 52480 bytes

// ---------------------------------------------------------------------------
// 2D DFT of an image-pair. ZT float4 = (re0, re1, im0, im1); read/written as
// ulonglong2 (packed pairs, no MOVs). D4 = (dre,dre,dim,dim); one XOR per
// entry builds -dim. 200 threads; both passes: thread t -> rows {t/20+10ri}
// (ri 0..3), cols {t%20+20ci} (ci 0..1). In-place between passes.
// Caller syncs after filling ZT; no trailing sync.
// ---------------------------------------------------------------------------
template <bool CONJ>
__device__ __forceinline__ void dft2d(
    float4 (*ZT)[IMG + 1], const float4 (*D4)[IMG + 1], int t,
    u64 outre[4][2], u64 outim[4][2])
{
    const int c2 = t % 20, r2 = t / 20;

    u64 are[4][2], aim[4][2];
    #pragma unroll
    for (int i = 0; i < 4; i++)
        #pragma unroll
        for (int j = 0; j < 2; j++) { are[i][j] = 0; aim[i][j] = 0; }

    // Pass 1: T(r,k) = sum_w Z(r,w) * D(k,w)
    #pragma unroll 4
    for (int w = 0; w < IMG; w++) {
        u64 zre[4], zim[4];
        #pragma unroll
        for (int ri = 0; ri < 4; ri++) {
            ulonglong2 z = *(const ulonglong2*)&ZT[r2 + 10 * ri][w];
            zre[ri] = z.x; zim[ri] = z.y;
        }
        #pragma unroll
        for (int ci = 0; ci < 2; ci++) {
            ulonglong2 d = *(const ulonglong2*)&D4[w][c2 + 20 * ci];
            u64 dre2 = d.x, dim2 = d.y, dnim2 = neg2(d.y);
            u64 mre = CONJ ? dim2 : dnim2;   // multiplies zim into re
            u64 mim = CONJ ? dnim2 : dim2;   // multiplies zre into im
            #pragma unroll
            for (int ri = 0; ri < 4; ri++) {
                fma2(are[ri][ci], zre[ri], dre2);
                fma2(are[ri][ci], zim[ri], mre);
                fma2(aim[ri][ci], zre[ri], mim);
                fma2(aim[ri][ci], zim[ri], dre2);
            }
        }
    }
    __syncthreads();   // all pass-1 reads done; overwrite ZT in place
    #pragma unroll
    for (int ri = 0; ri < 4; ri++)
        #pragma unroll
        for (int ci = 0; ci < 2; ci++) {
            ulonglong2 v; v.x = are[ri][ci]; v.y = aim[ri][ci];
            *(ulonglong2*)&ZT[r2 + 10 * ri][c2 + 20 * ci] = v;
        }
    __syncthreads();

    // Pass 2: out(r,k) = sum_h T(h,k) * D(r,h)
    #pragma unroll
    for (int i = 0; i < 4; i++)
        #pragma unroll
        for (int j = 0; j < 2; j++) { outre[i][j] = 0; outim[i][j] = 0; }

    #pragma unroll 4
    for (int h = 0; h < IMG; h++) {
        u64 tre[2], tim[2];
        #pragma unroll
        for (int ci = 0; ci < 2; ci++) {
            ulonglong2 z = *(const ulonglong2*)&ZT[h][c2 + 20 * ci];
            tre[ci] = z.x; tim[ci] = z.y;
        }
        #pragma unroll
        for (int ri = 0; ri < 4; ri++) {
            ulonglong2 d = *(const ulonglong2*)&D4[h][r2 + 10 * ri];
            u64 dre2 = d.x, dim2 = d.y, dnim2 = neg2(d.y);
            u64 mre = CONJ ? dim2 : dnim2;
            u64 mim = CONJ ? dnim2 : dim2;
            #pragma unroll
            for (int ci = 0; ci < 2; ci++) {
                fma2(outre[ri][ci], tre[ci], dre2);
                fma2(outre[ri][ci], tim[ci], mre);
                fma2(outim[ri][ci], tre[ci], mim);
                fma2(outim[ri][ci], tim[ci], dre2);
            }
        }
    }
}

__device__ __forceinline__ void load_D4_smem(float4 (*D4)[IMG + 1], int t) {
    #pragma unroll
    for (int r = 0; r < 8; r++) {
        int idx = t + 200 * r;
        D4[idx / IMG][idx % IMG] = g_D4[idx];
    }
}

// ---------------------------------------------------------------------------
// First: forward FFT of real input x (2 images/block) -> freq in DST.
// ---------------------------------------------------------------------------
template <int DST>
__global__ __launch_bounds__(200) void fft_first_kernel(const float* __restrict__ x)
{
    extern __shared__ float4 smem_raw[];
    float4 (*ZT)[IMG + 1] = (float4 (*)[IMG + 1])smem_raw;
    float4 (*D4)[IMG + 1] = (float4 (*)[IMG + 1])(smem_raw + IMG * (IMG + 1));
    const int t = threadIdx.x;
    const size_t i0 = (size_t)blockIdx.x * 2;
    load_D4_smem(D4, t);
    const float* in0 = x + i0 * HW;
    const float* in1 = in0 + HW;
    #pragma unroll
    for (int r = 0; r < 8; r++) {
        int idx = t + 200 * r;
        ZT[idx / IMG][idx % IMG] = make_float4(in0[idx], in1[idx], 0.f, 0.f);
    }
    __syncthreads();
    u64 re[4][2], im[4][2];
    dft2d<false>(ZT, D4, t, re, im);
    const int c2 = t % 20, r2 = t / 20;
    float2* o0 = getbuf<DST>() + i0 * HW;
    float2* o1 = o0 + HW;
    #pragma unroll
    for (int ri = 0; ri < 4; ri++)
        #pragma unroll
        for (int ci = 0; ci < 2; ci++) {
            int p = (r2 + 10 * ri) * IMG + (c2 + 20 * ci);
            float2 rf = unpack2(re[ri][ci]), mf = unpack2(im[ri][ci]);
            o0[p] = make_float2(rf.x, mf.x);
            o1[p] = make_float2(rf.y, mf.y);
        }
}

// ---------------------------------------------------------------------------
// Fused boundary: freq SRC -> ifft -> CReLU -> fft -> freq DST. 2 img/block.
// ---------------------------------------------------------------------------
template <int SRC, int DST>
__global__ __launch_bounds__(200) void fused_ifft_crelu_fft_kernel()
{
    extern __shared__ float4 smem_raw[];
    float4 (*ZT)[IMG + 1] = (float4 (*)[IMG + 1])smem_raw;
    float4 (*D4)[IMG + 1] = (float4 (*)[IMG + 1])(smem_raw + IMG * (IMG + 1));
    const int t = threadIdx.x;
    const size_t i0 = (size_t)blockIdx.x * 2;
    load_D4_smem(D4, t);
    const float2* in0 = getbuf<SRC>() + i0 * HW;
    const float2* in1 = in0 + HW;
    #pragma unroll
    for (int r = 0; r < 8; r++) {
        int idx = t + 200 * r;
        float2 v0 = in0[idx], v1 = in1[idx];
        ZT[idx / IMG][idx % IMG] = make_float4(v0.x, v1.x, v0.y, v1.y);
    }
    __syncthreads();

    u64 re[4][2], im[4][2];
    dft2d<true>(ZT, D4, t, re, im);     // inverse FFT

    const int c2 = t % 20, r2 = t / 20;
    __syncthreads();   // pass-2 reads done; safe to repack
    #pragma unroll
    for (int ri = 0; ri < 4; ri++)
        #pragma unroll
        for (int ci = 0; ci < 2; ci++) {
            float2 rf = unpack2(re[ri][ci]), mf = unpack2(im[ri][ci]);
            ulonglong2 v;
            v.x = pack2(fmaxf(rf.x, 0.f), fmaxf(rf.y, 0.f));
            v.y = pack2(fmaxf(mf.x, 0.f), fmaxf(mf.y, 0.f));
            *(ulonglong2*)&ZT[r2 + 10 * ri][c2 + 20 * ci] = v;
        }
    __syncthreads();

    dft2d<false>(ZT, D4, t, re, im);    // forward FFT

    float2* o0 = getbuf<DST>() + i0 * HW;
    float2* o1 = o0 + HW;
    #pragma unroll
    for (int ri = 0; ri < 4; ri++)
        #pragma unroll
        for (int ci = 0; ci < 2; ci++) {
            int p = (r2 + 10 * ri) * IMG + (c2 + 20 * ci);
            float2 rf = unpack2(re[ri][ci]), mf = unpack2(im[ri][ci]);
            o0[p] = make_float2(rf.x, mf.x);
            o1[p] = make_float2(rf.y, mf.y);
        }
}

// ---------------------------------------------------------------------------
// Last: inverse FFT (2 images/block), write real part to harness output.
// ---------------------------------------------------------------------------
template <int SRC>
__global__ __launch_bounds__(200) void ifft_last_kernel(float* __restrict__ outp)
{
    extern __shared__ float4 smem_raw[];
    float4 (*ZT)[IMG + 1] = (float4 (*)[IMG + 1])smem_raw;
    float4 (*D4)[IMG + 1] = (float4 (*)[IMG + 1])(smem_raw + IMG * (IMG + 1));
    const int t = threadIdx.x;
    const size_t i0 = (size_t)blockIdx.x * 2;
    load_D4_smem(D4, t);
    const float2* in0 = getbuf<SRC>() + i0 * HW;
    const float2* in1 = in0 + HW;
    #pragma unroll
    for (int r = 0; r < 8; r++) {
        int idx = t + 200 * r;
        float2 v0 = in0[idx], v1 = in1[idx];
        ZT[idx / IMG][idx % IMG] = make_float4(v0.x, v1.x, v0.y, v1.y);
    }
    __syncthreads();
    u64 re[4][2], im[4][2];
    dft2d<true>(ZT, D4, t, re, im);
    const int c2 = t % 20, r2 = t / 20;
    float* o0 = outp + i0 * HW;
    float* o1 = o0 + HW;
    #pragma unroll
    for (int ri = 0; ri < 4; ri++)
        #pragma unroll
        for (int ci = 0; ci < 2; ci++) {
            int p = (r2 + 10 * ri) * IMG + (c2 + 20 * ci);
            float2 rf = unpack2(re[ri][ci]);
            o0[p] = rf.x;
            o1[p] = rf.y;
        }
}

// ---------------------------------------------------------------------------
// mix40, double-buffered (R8 version): O[b,o,hw] = sum_i F[b,i,hw]*W[i,o,hw].
// ---------------------------------------------------------------------------
__device__ __forceinline__ void cmac(float2& a, float2 z, float2 d) {
    a.x = fmaf(z.x, d.x, a.x);
    a.x = fmaf(-z.y, d.y, a.x);
    a.y = fmaf(z.x, d.y, a.y);
    a.y = fmaf(z.y, d.x, a.y);
}

#define MIXSMEM (2 * (1024 + 2560) * 8)   // 57344 bytes

template <int SRC, int DST>
__global__ __launch_bounds__(640, 1) void mix40_kernel(const float2* __restrict__ W)
{
    extern __shared__ float2 sm[];
    const float2* F = getbuf<SRC>();
    float2* O = getbuf<DST>();

    const int tid  = threadIdx.x;
    const int lane = tid & 31;
    const int warp = tid >> 5;
    const int bq   = (warp & 3) * 4;
    const int oq   = (warp >> 2) * 8;
    const int hw0  = blockIdx.x * 32;
    const int b0   = blockIdx.y * 16;

    const int fb = tid >> 6, frem = tid & 63;
    const int fii = frem >> 5, fhw = frem & 31;
    const int f1 = tid + 640;
    const int f1b = f1 >> 6, f1rem = f1 & 63;
    const int f1ii = f1rem >> 5, f1hw = f1rem & 31;

    float2 acc[4][8];
    #pragma unroll
    for (int b = 0; b < 4; b++)
        #pragma unroll
        for (int o = 0; o < 8; o++)
            acc[b][o] = make_float2(0.f, 0.f);

    {
        float2* Fs = sm;
        float2* Ws = sm + 1024;
        Fs[tid] = F[((size_t)(b0 + fb) * CH + fii) * HW + hw0 + fhw];
        if (f1 < 1024)
            Fs[f1] = F[((size_t)(b0 + f1b) * CH + f1ii) * HW + hw0 + f1hw];
        #pragma unroll
        for (int rep = 0; rep < 4; rep++) {
            int idx = tid + rep * 640;
            int ii = idx / 1280, rem = idx % 1280;
            int o = rem >> 5, hw = rem & 31;
            Ws[idx] = W[((size_t)ii * CH + o) * HW + hw0 + hw];
        }
    }
    __syncthreads();

    for (int chunk = 0; chunk < 20; chunk++) {
        const int cur = chunk & 1;
        float2* Fs = sm + cur * 3584;
        float2* Ws = sm + cur * 3584 + 1024;

        float2 pf0, pf1, pw[4];
        if (chunk < 19) {
            const int i0n = (chunk + 1) * 2;
            pf0 = F[((size_t)(b0 + fb) * CH + i0n + fii) * HW + hw0 + fhw];
            if (f1 < 1024)
                pf1 = F[((size_t)(b0 + f1b) * CH + i0n + f1ii) * HW + hw0 + f1hw];
            #pragma unroll
            for (int rep = 0; rep < 4; rep++) {
                int idx = tid + rep * 640;
                int ii = idx / 1280, rem = idx % 1280;
                int o = rem >> 5, hw = rem & 31;
                pw[rep] = W[((size_t)(i0n + ii) * CH + o) * HW + hw0 + hw];
            }
        }

        #pragma unroll
        for (int ii = 0; ii < 2; ii++) {
            float2 f[4], wv[8];
            #pragma unroll
            for (int b = 0; b < 4; b++) f[b] = Fs[((bq + b) * 2 + ii) * 32 + lane];
            #pragma unroll
            for (int o = 0; o < 8; o++) wv[o] = Ws[(ii * 40 + oq + o) * 32 + lane];
            #pragma unroll
            for (int b = 0; b < 4; b++)
                #pragma unroll
                for (int o = 0; o < 8; o++)
                    cmac(acc[b][o], f[b], wv[o]);
        }

        if (chunk < 19) {
            float2* Fn = sm + (1 - cur) * 3584;
            float2* Wn = Fn + 1024;
            Fn[tid] = pf0;
            if (f1 < 1024) Fn[f1] = pf1;
            #pragma unroll
            for (int rep = 0; rep < 4; rep++)
                Wn[tid + rep * 640] = pw[rep];
        }
        __syncthreads();
    }

    #pragma unroll
    for (int b = 0; b < 4; b++)
        #pragma unroll
        for (int o = 0; o < 8; o++)
            O[((size_t)(b0 + bq + b) * CH + oq + o) * HW + hw0 + lane] = acc[b][o];
}

// Layer-1 mix (inC=1): O[b,o,hw] = F[b,hw] * W1[o,hw]. Fully coalesced.
template <int SRC, int DST>
__global__ __launch_bounds__(400) void mix1_kernel(const float2* __restrict__ W)
{
    const float2* F = getbuf<SRC>();
    float2* O = getbuf<DST>();
    const int o = blockIdx.x;
    const int b = blockIdx.y;
    #pragma unroll
    for (int r = 0; r < 4; r++) {
        int hw = threadIdx.x + 400 * r;
        float2 f = F[(size_t)b * HW + hw];
        float2 w = W[(size_t)o * HW + hw];
        float2 acc;
        acc.x = f.x * w.x - f.y * w.y;
        acc.y = f.x * w.y + f.y * w.x;
        O[((size_t)b * CH + o) * HW + hw] = acc;
    }
}

// Layer-6 mix (outC=1): O[b,hw] = sum_i F[b,i,hw] * W6[i,hw]. Coalesced.
template <int SRC, int DST>
__global__ __launch_bounds__(400) void mix6_kernel(const float2* __restrict__ W)
{
    const float2* F = getbuf<SRC>();
    float2* O = getbuf<DST>();
    const int b = blockIdx.x;
    #pragma unroll
    for (int r = 0; r < 4; r++) {
        int hw = threadIdx.x + 400 * r;
        float2 acc = {0, 0};
        #pragma unroll 8
        for (int i = 0; i < CH; i++) {
            float2 f = F[((size_t)b * CH + i) * HW + hw];
            float2 w = W[(size_t)i * HW + hw];
            cmac(acc, f, w);
        }
        O[(size_t)b * HW + hw] = acc;
    }
}

extern "C" void kernel_launch(void* const* d_in, const int* in_sizes, int n_in,
                              void* d_out, int out_size)
{
    const float*  x  = (const float*)d_in[0];
    const float2* w1 = (const float2*)d_in[1];
    const float2* w2 = (const float2*)d_in[2];
    const float2* w3 = (const float2*)d_in[3];
    const float2* w4 = (const float2*)d_in[4];
    const float2* w5 = (const float2*)d_in[5];
    const float2* w6 = (const float2*)d_in[6];
    float* out = (float*)d_out;

    cudaFuncSetAttribute(fft_first_kernel<0>,
                         cudaFuncAttributeMaxDynamicSharedMemorySize, FFTSMEM);
    cudaFuncSetAttribute(fused_ifft_crelu_fft_kernel<1, 0>,
                         cudaFuncAttributeMaxDynamicSharedMemorySize, FFTSMEM);
    cudaFuncSetAttribute(ifft_last_kernel<1>,
                         cudaFuncAttributeMaxDynamicSharedMemorySize, FFTSMEM);
    cudaFuncSetAttribute(mix40_kernel<0, 1>,
                         cudaFuncAttributeMaxDynamicSharedMemorySize, MIXSMEM);

    const int nPair = BATCH * CH / 2;          // 5120 fused blocks
    const dim3 mixGrid(HW / 32, BATCH / 16);   // (50, 16)
    const dim3 mix1Grid(CH, BATCH);

    init_D_kernel<<<4, 400>>>();

    // Layer 1 (inC=1 -> outC=40)
    fft_first_kernel<0><<<BATCH / 2, 200, FFTSMEM>>>(x);
    mix1_kernel<0, 1><<<mix1Grid, 400>>>(w1);
    fused_ifft_crelu_fft_kernel<1, 0><<<nPair, 200, FFTSMEM>>>();

    // Layer 2
    mix40_kernel<0, 1><<<mixGrid, 640, MIXSMEM>>>(w2);
    fused_ifft_crelu_fft_kernel<1, 0><<<nPair, 200, FFTSMEM>>>();

    // Layer 3
    mix40_kernel<0, 1><<<mixGrid, 640, MIXSMEM>>>(w3);
    fused_ifft_crelu_fft_kernel<1, 0><<<nPair, 200, FFTSMEM>>>();

    // Layer 4
    mix40_kernel<0, 1><<<mixGrid, 640, MIXSMEM>>>(w4);
    fused_ifft_crelu_fft_kernel<1, 0><<<nPair, 200, FFTSMEM>>>();

    // Layer 5
    mix40_kernel<0, 1><<<mixGrid, 640, MIXSMEM>>>(w5);
    fused_ifft_crelu_fft_kernel<1, 0><<<nPair, 200, FFTSMEM>>>();

    // Layer 6 (inC=40 -> outC=1), final output = real(ifft2)
    mix6_kernel<0, 1><<<BATCH, 400>>>(w6);
    ifft_last_kernel<1><<<BATCH / 2, 200, FFTSMEM>>>(out);
}

// round 11
// speedup vs baseline: 1.1864x; 1.1864x over previous
#include <cuda_runtime.h>
#include <math.h>

#define IMG 40
#define HW 1600
#define BATCH 256
#define CH 40

typedef unsigned long long u64;

// Ping-pong scratch (131 MB each), device-side only.
__device__ float2 g_bufA[(size_t)BATCH * CH * HW];
__device__ float2 g_bufB[(size_t)BATCH * CH * HW];
__device__ float2 g_D[HW];   // forward DFT matrix (ortho norm per 1D pass)

template <int B>
__device__ __forceinline__ float2* getbuf() {
    return (B == 0) ? g_bufA : g_bufB;
}

__global__ void init_D_kernel() {
    int idx = blockIdx.x * blockDim.x + threadIdx.x;
    if (idx >= HW) return;
    int k = idx / IMG, n = idx % IMG;
    int m = (k * n) % IMG;
    float theta = 2.0f * 3.14159265358979323846f * (float)m / (float)IMG;
    float s, c;
    sincosf(theta, &s, &c);
    float nrm = rsqrtf((float)IMG);
    g_D[idx] = make_float2(c * nrm, -s * nrm);
}

// ---------------- packed f32x2 helpers ----------------
__device__ __forceinline__ u64 pack2(float lo, float hi) {
    u64 r; asm("mov.b64 %0, {%1, %2};" : "=l"(r) : "f"(lo), "f"(hi)); return r;
}
__device__ __forceinline__ float2 unpack2(u64 v) {
    float lo, hi; asm("mov.b64 {%0, %1}, %2;" : "=f"(lo), "=f"(hi) : "l"(v));
    return make_float2(lo, hi);
}
__device__ __forceinline__ void fma2(u64& a, u64 x, u64 y) {
    asm("fma.rn.f32x2 %0, %1, %2, %0;" : "+l"(a) : "l"(x), "l"(y));
}
__device__ __forceinline__ u64 neg2(u64 a) {   // flip both packed sign bits
    u64 r;
    asm("xor.b64 %0, %1, %2;" : "=l"(r) : "l"(a), "l"(0x8000000080000000ULL));
    return r;
}

// ---------------------------------------------------------------------------
// R5 2D DFT core (verified fastest). ZT float4 = (re0, re1, im0, im1),
// 200 threads. Pass 1: thread t -> rows {t/10, t/10+20}, cols {t%10+10ci}
// (ci 0..3). Pass 2 (remapped): rows {t/20+10ri} (ri 0..3), cols {t%20+20ci}
// (ci 0..1). Conj = operand-role swap of (dim,-dim) — exact fp32.
// In-place: T overwrites ZT. Caller syncs after filling ZT; no trailing sync.
// Output: outre/outim[ri][ci] packed (img0,img1) at (t/20+10ri, t%20+20ci).
// ---------------------------------------------------------------------------
template <bool CONJ>
__device__ __forceinline__ void dft2d(
    float4 (*ZT)[IMG + 1], const float2 (*Ds)[IMG + 1], int t,
    u64 outre[4][2], u64 outim[4][2])
{
    const int c0 = t % 10, r0 = t / 10;

    u64 are[2][4], aim[2][4];
    #pragma unroll
    for (int i = 0; i < 2; i++)
        #pragma unroll
        for (int j = 0; j < 4; j++) { are[i][j] = 0; aim[i][j] = 0; }

    // Pass 1: T(r,k) = sum_w Z(r,w) * D(k,w)
    #pragma unroll 4
    for (int w = 0; w < IMG; w++) {
        float4 za = ZT[r0][w];
        float4 zb = ZT[r0 + 20][w];
        u64 zreA = pack2(za.x, za.y), zimA = pack2(za.z, za.w);
        u64 zreB = pack2(zb.x, zb.y), zimB = pack2(zb.z, zb.w);
        #pragma unroll
        for (int ci = 0; ci < 4; ci++) {
            float2 d = Ds[w][c0 + 10 * ci];
            u64 dre2  = pack2(d.x, d.x);
            u64 dim2  = pack2(d.y, d.y);
            u64 dnim2 = neg2(dim2);
            u64 mre = CONJ ? dim2 : dnim2;   // multiplies zim into re
            u64 mim = CONJ ? dnim2 : dim2;   // multiplies zre into im
            fma2(are[0][ci], zreA, dre2);
            fma2(are[0][ci], zimA, mre);
            fma2(aim[0][ci], zreA, mim);
            fma2(aim[0][ci], zimA, dre2);
            fma2(are[1][ci], zreB, dre2);
            fma2(are[1][ci], zimB, mre);
            fma2(aim[1][ci], zreB, mim);
            fma2(aim[1][ci], zimB, dre2);
        }
    }
    __syncthreads();   // all pass-1 reads done; overwrite ZT in place
    #pragma unroll
    for (int ri = 0; ri < 2; ri++)
        #pragma unroll
        for (int ci = 0; ci < 4; ci++) {
            float2 rf = unpack2(are[ri][ci]), mf = unpack2(aim[ri][ci]);
            ZT[r0 + 20 * ri][c0 + 10 * ci] = make_float4(rf.x, rf.y, mf.x, mf.y);
        }
    __syncthreads();

    // Pass 2: out(r,k) = sum_h T(h,k) * D(r,h), remapped 4 rows x 2 cols.
    const int c2 = t % 20, r2 = t / 20;
    #pragma unroll
    for (int i = 0; i < 4; i++)
        #pragma unroll
        for (int j = 0; j < 2; j++) { outre[i][j] = 0; outim[i][j] = 0; }

    #pragma unroll 4
    for (int h = 0; h < IMG; h++) {
        float4 t0 = ZT[h][c2];
        float4 t1 = ZT[h][c2 + 20];
        u64 tre0 = pack2(t0.x, t0.y), tim0 = pack2(t0.z, t0.w);
        u64 tre1 = pack2(t1.x, t1.y), tim1 = pack2(t1.z, t1.w);
        #pragma unroll
        for (int ri = 0; ri < 4; ri++) {
            float2 d = Ds[h][r2 + 10 * ri];
            u64 dre2  = pack2(d.x, d.x);
            u64 dim2  = pack2(d.y, d.y);
            u64 dnim2 = neg2(dim2);
            u64 mre = CONJ ? dim2 : dnim2;
            u64 mim = CONJ ? dnim2 : dim2;
            fma2(outre[ri][0], tre0, dre2);
            fma2(outre[ri][0], tim0, mre);
            fma2(outim[ri][0], tre0, mim);
            fma2(outim[ri][0], tim0, dre2);
            fma2(outre[ri][1], tre1, dre2);
            fma2(outre[ri][1], tim1, mre);
            fma2(outim[ri][1], tre1, mim);
            fma2(outim[ri][1], tim1, dre2);
        }
    }
}

__device__ __forceinline__ void load_D_smem(float2 (*Ds)[IMG + 1], int t) {
    #pragma unroll
    for (int r = 0; r < 8; r++) {
        int idx = t + 200 * r;
        Ds[idx / IMG][idx % IMG] = g_D[idx];
    }
}

// ---------------------------------------------------------------------------
// First: forward FFT of real input x (2 images/block) -> freq in DST.
// ---------------------------------------------------------------------------
template <int DST>
__global__ __launch_bounds__(200, 4) void fft_first_kernel(const float* __restrict__ x)
{
    __shared__ float4 ZT[IMG][IMG + 1];
    __shared__ float2 Ds[IMG][IMG + 1];
    const int t = threadIdx.x;
    const size_t i0 = (size_t)blockIdx.x * 2;
    load_D_smem(Ds, t);
    const float* in0 = x + i0 * HW;
    const float* in1 = in0 + HW;
    #pragma unroll
    for (int r = 0; r < 8; r++) {
        int idx = t + 200 * r;
        ZT[idx / IMG][idx % IMG] = make_float4(in0[idx], in1[idx], 0.f, 0.f);
    }
    __syncthreads();
    u64 re[4][2], im[4][2];
    dft2d<false>(ZT, Ds, t, re, im);
    const int c2 = t % 20, r2 = t / 20;
    float2* o0 = getbuf<DST>() + i0 * HW;
    float2* o1 = o0 + HW;
    #pragma unroll
    for (int ri = 0; ri < 4; ri++)
        #pragma unroll
        for (int ci = 0; ci < 2; ci++) {
            int p = (r2 + 10 * ri) * IMG + (c2 + 20 * ci);
            float2 rf = unpack2(re[ri][ci]), mf = unpack2(im[ri][ci]);
            o0[p] = make_float2(rf.x, mf.x);
            o1[p] = make_float2(rf.y, mf.y);
        }
}

// ---------------------------------------------------------------------------
// Fused layer-1: mix1 folded into the boundary kernel.
// Block = (b, o-pair): z_o = A[b] * W1[o] computed during the load loop
// (A is 3.3 MB, L2-resident across the 20 o-pairs of each b), then
// ifft -> CReLU -> fft identical to the plain fused kernel.
// ---------------------------------------------------------------------------
template <int SRC, int DST>
__global__ __launch_bounds__(200, 4) void fused1_mix_ifft_crelu_fft_kernel(
    const float2* __restrict__ W1)
{
    __shared__ float4 ZT[IMG][IMG + 1];
    __shared__ float2 Ds[IMG][IMG + 1];
    const int t = threadIdx.x;
    const int b  = blockIdx.x / 20;
    const int op = blockIdx.x % 20;
    const int o0 = 2 * op;
    load_D_smem(Ds, t);
    const float2* A  = getbuf<SRC>() + (size_t)b * HW;   // freq of x[b]
    const float2* w0 = W1 + (size_t)o0 * HW;
    const float2* w1 = w0 + HW;
    #pragma unroll
    for (int r = 0; r < 8; r++) {
        int idx = t + 200 * r;
        float2 a = A[idx];
        float2 u = w0[idx], v = w1[idx];
        float z0re = a.x * u.x - a.y * u.y;
        float z0im = a.x * u.y + a.y * u.x;
        float z1re = a.x * v.x - a.y * v.y;
        float z1im = a.x * v.y + a.y * v.x;
        ZT[idx / IMG][idx % IMG] = make_float4(z0re, z1re, z0im, z1im);
    }
    __syncthreads();

    u64 re[4][2], im[4][2];
    dft2d<true>(ZT, Ds, t, re, im);     // inverse FFT

    const int c2 = t % 20, r2 = t / 20;
    __syncthreads();
    #pragma unroll
    for (int ri = 0; ri < 4; ri++)
        #pragma unroll
        for (int ci = 0; ci < 2; ci++) {
            float2 rf = unpack2(re[ri][ci]), mf = unpack2(im[ri][ci]);
            ZT[r2 + 10 * ri][c2 + 20 * ci] = make_float4(
                fmaxf(rf.x, 0.f), fmaxf(rf.y, 0.f),
                fmaxf(mf.x, 0.f), fmaxf(mf.y, 0.f));
        }
    __syncthreads();

    dft2d<false>(ZT, Ds, t, re, im);    // forward FFT

    float2* out0 = getbuf<DST>() + ((size_t)b * CH + o0) * HW;
    float2* out1 = out0 + HW;
    #pragma unroll
    for (int ri = 0; ri < 4; ri++)
        #pragma unroll
        for (int ci = 0; ci < 2; ci++) {
            int p = (r2 + 10 * ri) * IMG + (c2 + 20 * ci);
            float2 rf = unpack2(re[ri][ci]), mf = unpack2(im[ri][ci]);
            out0[p] = make_float2(rf.x, mf.x);
            out1[p] = make_float2(rf.y, mf.y);
        }
}

// ---------------------------------------------------------------------------
// Fused boundary: freq SRC -> ifft -> CReLU -> fft -> freq DST. 2 img/block.
// ---------------------------------------------------------------------------
template <int SRC, int DST>
__global__ __launch_bounds__(200, 4) void fused_ifft_crelu_fft_kernel()
{
    __shared__ float4 ZT[IMG][IMG + 1];
    __shared__ float2 Ds[IMG][IMG + 1];
    const int t = threadIdx.x;
    const size_t i0 = (size_t)blockIdx.x * 2;
    load_D_smem(Ds, t);
    const float2* in0 = getbuf<SRC>() + i0 * HW;
    const float2* in1 = in0 + HW;
    #pragma unroll
    for (int r = 0; r < 8; r++) {
        int idx = t + 200 * r;
        float2 v0 = in0[idx], v1 = in1[idx];
        ZT[idx / IMG][idx % IMG] = make_float4(v0.x, v1.x, v0.y, v1.y);
    }
    __syncthreads();

    u64 re[4][2], im[4][2];
    dft2d<true>(ZT, Ds, t, re, im);     // inverse FFT

    const int c2 = t % 20, r2 = t / 20;
    __syncthreads();
    #pragma unroll
    for (int ri = 0; ri < 4; ri++)
        #pragma unroll
        for (int ci = 0; ci < 2; ci++) {
            float2 rf = unpack2(re[ri][ci]), mf = unpack2(im[ri][ci]);
            ZT[r2 + 10 * ri][c2 + 20 * ci] = make_float4(
                fmaxf(rf.x, 0.f), fmaxf(rf.y, 0.f),
                fmaxf(mf.x, 0.f), fmaxf(mf.y, 0.f));
        }
    __syncthreads();

    dft2d<false>(ZT, Ds, t, re, im);    // forward FFT

    float2* o0 = getbuf<DST>() + i0 * HW;
    float2* o1 = o0 + HW;
    #pragma unroll
    for (int ri = 0; ri < 4; ri++)
        #pragma unroll
        for (int ci = 0; ci < 2; ci++) {
            int p = (r2 + 10 * ri) * IMG + (c2 + 20 * ci);
            float2 rf = unpack2(re[ri][ci]), mf = unpack2(im[ri][ci]);
            o0[p] = make_float2(rf.x, mf.x);
            o1[p] = make_float2(rf.y, mf.y);
        }
}

// ---------------------------------------------------------------------------
// Last: inverse FFT (2 images/block), write real part to harness output.
// ---------------------------------------------------------------------------
template <int SRC>
__global__ __launch_bounds__(200, 4) void ifft_last_kernel(float* __restrict__ outp)
{
    __shared__ float4 ZT[IMG][IMG + 1];
    __shared__ float2 Ds[IMG][IMG + 1];
    const int t = threadIdx.x;
    const size_t i0 = (size_t)blockIdx.x * 2;
    load_D_smem(Ds, t);
    const float2* in0 = getbuf<SRC>() + i0 * HW;
    const float2* in1 = in0 + HW;
    #pragma unroll
    for (int r = 0; r < 8; r++) {
        int idx = t + 200 * r;
        float2 v0 = in0[idx], v1 = in1[idx];
        ZT[idx / IMG][idx % IMG] = make_float4(v0.x, v1.x, v0.y, v1.y);
    }
    __syncthreads();
    u64 re[4][2], im[4][2];
    dft2d<true>(ZT, Ds, t, re, im);
    const int c2 = t % 20, r2 = t / 20;
    float* o0 = outp + i0 * HW;
    float* o1 = o0 + HW;
    #pragma unroll
    for (int ri = 0; ri < 4; ri++)
        #pragma unroll
        for (int ci = 0; ci < 2; ci++) {
            int p = (r2 + 10 * ri) * IMG + (c2 + 20 * ci);
            float2 rf = unpack2(re[ri][ci]);
            o0[p] = rf.x;
            o1[p] = rf.y;
        }
}

// ---------------------------------------------------------------------------
// mix40, double-buffered (R8): O[b,o,hw] = sum_i F[b,i,hw]*W[i,o,hw].
// ---------------------------------------------------------------------------
__device__ __forceinline__ void cmac(float2& a, float2 z, float2 d) {
    a.x = fmaf(z.x, d.x, a.x);
    a.x = fmaf(-z.y, d.y, a.x);
    a.y = fmaf(z.x, d.y, a.y);
    a.y = fmaf(z.y, d.x, a.y);
}

#define MIXSMEM (2 * (1024 + 2560) * 8)   // 57344 bytes

template <int SRC, int DST>
__global__ __launch_bounds__(640, 1) void mix40_kernel(const float2* __restrict__ W)
{
    extern __shared__ float2 sm[];
    const float2* F = getbuf<SRC>();
    float2* O = getbuf<DST>();

    const int tid  = threadIdx.x;
    const int lane = tid & 31;
    const int warp = tid >> 5;
    const int bq   = (warp & 3) * 4;
    const int oq   = (warp >> 2) * 8;
    const int hw0  = blockIdx.x * 32;
    const int b0   = blockIdx.y * 16;

    const int fb = tid >> 6, frem = tid & 63;
    const int fii = frem >> 5, fhw = frem & 31;
    const int f1 = tid + 640;
    const int f1b = f1 >> 6, f1rem = f1 & 63;
    const int f1ii = f1rem >> 5, f1hw = f1rem & 31;

    float2 acc[4][8];
    #pragma unroll
    for (int b = 0; b < 4; b++)
        #pragma unroll
        for (int o = 0; o < 8; o++)
            acc[b][o] = make_float2(0.f, 0.f);

    {
        float2* Fs = sm;
        float2* Ws = sm + 1024;
        Fs[tid] = F[((size_t)(b0 + fb) * CH + fii) * HW + hw0 + fhw];
        if (f1 < 1024)
            Fs[f1] = F[((size_t)(b0 + f1b) * CH + f1ii) * HW + hw0 + f1hw];
        #pragma unroll
        for (int rep = 0; rep < 4; rep++) {
            int idx = tid + rep * 640;
            int ii = idx / 1280, rem = idx % 1280;
            int o = rem >> 5, hw = rem & 31;
            Ws[idx] = W[((size_t)ii * CH + o) * HW + hw0 + hw];
        }
    }
    __syncthreads();

    for (int chunk = 0; chunk < 20; chunk++) {
        const int cur = chunk & 1;
        float2* Fs = sm + cur * 3584;
        float2* Ws = sm + cur * 3584 + 1024;

        float2 pf0, pf1, pw[4];
        if (chunk < 19) {
            const int i0n = (chunk + 1) * 2;
            pf0 = F[((size_t)(b0 + fb) * CH + i0n + fii) * HW + hw0 + fhw];
            if (f1 < 1024)
                pf1 = F[((size_t)(b0 + f1b) * CH + i0n + f1ii) * HW + hw0 + f1hw];
            #pragma unroll
            for (int rep = 0; rep < 4; rep++) {
                int idx = tid + rep * 640;
                int ii = idx / 1280, rem = idx % 1280;
                int o = rem >> 5, hw = rem & 31;
                pw[rep] = W[((size_t)(i0n + ii) * CH + o) * HW + hw0 + hw];
            }
        }

        #pragma unroll
        for (int ii = 0; ii < 2; ii++) {
            float2 f[4], wv[8];
            #pragma unroll
            for (int b = 0; b < 4; b++) f[b] = Fs[((bq + b) * 2 + ii) * 32 + lane];
            #pragma unroll
            for (int o = 0; o < 8; o++) wv[o] = Ws[(ii * 40 + oq + o) * 32 + lane];
            #pragma unroll
            for (int b = 0; b < 4; b++)
                #pragma unroll
                for (int o = 0; o < 8; o++)
                    cmac(acc[b][o], f[b], wv[o]);
        }

        if (chunk < 19) {
            float2* Fn = sm + (1 - cur) * 3584;
            float2* Wn = Fn + 1024;
            Fn[tid] = pf0;
            if (f1 < 1024) Fn[f1] = pf1;
            #pragma unroll
            for (int rep = 0; rep < 4; rep++)
                Wn[tid + rep * 640] = pw[rep];
        }
        __syncthreads();
    }

    #pragma unroll
    for (int b = 0; b < 4; b++)
        #pragma unroll
        for (int o = 0; o < 8; o++)
            O[((size_t)(b0 + bq + b) * CH + oq + o) * HW + hw0 + lane] = acc[b][o];
}

// Layer-6 mix (outC=1): O[b,hw] = sum_i F[b,i,hw] * W6[i,hw]. Coalesced.
template <int SRC, int DST>
__global__ __launch_bounds__(400) void mix6_kernel(const float2* __restrict__ W)
{
    const float2* F = getbuf<SRC>();
    float2* O = getbuf<DST>();
    const int b = blockIdx.x;
    #pragma unroll
    for (int r = 0; r < 4; r++) {
        int hw = threadIdx.x + 400 * r;
        float2 acc = {0, 0};
        #pragma unroll 8
        for (int i = 0; i < CH; i++) {
            float2 f = F[((size_t)b * CH + i) * HW + hw];
            float2 w = W[(size_t)i * HW + hw];
            cmac(acc, f, w);
        }
        O[(size_t)b * HW + hw] = acc;
    }
}

extern "C" void kernel_launch(void* const* d_in, const int* in_sizes, int n_in,
                              void* d_out, int out_size)
{
    const float*  x  = (const float*)d_in[0];
    const float2* w1 = (const float2*)d_in[1];
    const float2* w2 = (const float2*)d_in[2];
    const float2* w3 = (const float2*)d_in[3];
    const float2* w4 = (const float2*)d_in[4];
    const float2* w5 = (const float2*)d_in[5];
    const float2* w6 = (const float2*)d_in[6];
    float* out = (float*)d_out;

    // Opt-in for the EXACT instantiation launched below (mix40_kernel<1,0>).
    cudaFuncSetAttribute(mix40_kernel<1, 0>,
                         cudaFuncAttributeMaxDynamicSharedMemorySize, MIXSMEM);

    const int nPair = BATCH * CH / 2;          // 5120 fused blocks
    const dim3 mixGrid(HW / 32, BATCH / 16);   // (50, 16)

    init_D_kernel<<<4, 400>>>();

    // Layer 1 (inC=1 -> outC=40): fft, then mix1 fused into the boundary.
    fft_first_kernel<0><<<BATCH / 2, 200>>>(x);              // x -> A (freq)
    fused1_mix_ifft_crelu_fft_kernel<0, 1><<<nPair, 200>>>(w1);  // A,W1 -> B

    // Layer 2
    mix40_kernel<1, 0><<<mixGrid, 640, MIXSMEM>>>(w2);       // B -> A
    fused_ifft_crelu_fft_kernel<0, 1><<<nPair, 200>>>();     // A -> B

    // Layer 3
    mix40_kernel<1, 0><<<mixGrid, 640, MIXSMEM>>>(w3);
    fused_ifft_crelu_fft_kernel<0, 1><<<nPair, 200>>>();

    // Layer 4
    mix40_kernel<1, 0><<<mixGrid, 640, MIXSMEM>>>(w4);
    fused_ifft_crelu_fft_kernel<0, 1><<<nPair, 200>>>();

    // Layer 5
    mix40_kernel<1, 0><<<mixGrid, 640, MIXSMEM>>>(w5);
    fused_ifft_crelu_fft_kernel<0, 1><<<nPair, 200>>>();     // A -> B

    // Layer 6 (inC=40 -> outC=1), final output = real(ifft2)
    mix6_kernel<1, 0><<<BATCH, 400>>>(w6);                   // B -> A
    ifft_last_kernel<0><<<BATCH / 2, 200>>>(out);            // A -> out
}